// round 11
// baseline (speedup 1.0000x reference)
#include <cuda_runtime.h>
#include <cuda_bf16.h>
#include <math.h>
#include <stdint.h>

// ---------------- problem constants ------------------------------------------
#define TT   8192
#define KK   2
#define HH   1024
#define II   2816
#define EE   8
#define TKN  (TT*KK)          // 16384 assignments
#define TM   128              // rows per GEMM tile
#define NT_MAX (TKN/TM + EE)  // 136 row tiles max
#define PAD  256

// GEMM tiling: swizzled smem, no padding
#define BK    32
#define PLANE (128*64)        // 8192 B per operand plane (128 rows x 64 B)
#define STAGE (4*PLANE)       // 32768 B per pipeline stage
#define NSTG  3
#define SMEM_BYTES (NSTG*STAGE)  // 98304 B

// ---------------- device scratch ---------------------------------------------
__device__ int   g_offsets[EE + 1];
__device__ int   g_slot_token[TKN + PAD];
__device__ int   g_tok_slot[TKN];
__device__ int   g_tile_expert[NT_MAX];
__device__ int   g_tile_row[NT_MAX];
__device__ int   g_num_tiles;

__device__ __align__(256) __nv_bfloat16 g_xg_hi[(size_t)(TKN + PAD) * HH];
__device__ __align__(256) __nv_bfloat16 g_xg_lo[(size_t)(TKN + PAD) * HH];
// w13 transposed, gate/up interleaved: n=2i -> gate col i, n=2i+1 -> up col i
__device__ __align__(256) __nv_bfloat16 g_w13i_hi[(size_t)EE * 2 * II * HH];
__device__ __align__(256) __nv_bfloat16 g_w13i_lo[(size_t)EE * 2 * II * HH];
__device__ __align__(256) __nv_bfloat16 g_w2t_hi[(size_t)EE * HH * II];
__device__ __align__(256) __nv_bfloat16 g_w2t_lo[(size_t)EE * HH * II];
__device__ __align__(256) __nv_bfloat16 g_h_hi[(size_t)(TKN + PAD) * II];
__device__ __align__(256) __nv_bfloat16 g_h_lo[(size_t)(TKN + PAD) * II];
__device__ __align__(256) float         g_y[(size_t)(TKN + PAD) * HH];

// ---------------- helpers ----------------------------------------------------
__device__ __forceinline__ uint32_t smem_u32(const void* p) {
    uint32_t a;
    asm("{ .reg .u64 t; cvta.to.shared.u64 t, %1; cvt.u32.u64 %0, t; }" : "=r"(a) : "l"(p));
    return a;
}

__device__ __forceinline__ void ldmx4(uint32_t* r, uint32_t addr) {
    asm volatile("ldmatrix.sync.aligned.m8n8.x4.shared.b16 {%0,%1,%2,%3}, [%4];"
        : "=r"(r[0]), "=r"(r[1]), "=r"(r[2]), "=r"(r[3]) : "r"(addr));
}

__device__ __forceinline__ void mma16816(float* d, const uint32_t* a, const uint32_t* b) {
    asm volatile("mma.sync.aligned.m16n8k16.row.col.f32.bf16.bf16.f32 "
        "{%0,%1,%2,%3}, {%4,%5,%6,%7}, {%8,%9}, {%0,%1,%2,%3};"
        : "+f"(d[0]), "+f"(d[1]), "+f"(d[2]), "+f"(d[3])
        : "r"(a[0]), "r"(a[1]), "r"(a[2]), "r"(a[3]), "r"(b[0]), "r"(b[1]));
}

__device__ __forceinline__ uint32_t pack_h(float g, float u) {
    float h = u * (g / (1.0f + __expf(-g)));
    __nv_bfloat16 hh = __float2bfloat16(h);
    __nv_bfloat16 hl = __float2bfloat16(h - __bfloat162float(hh));
    return (uint32_t)__bfloat16_as_ushort(hh) | ((uint32_t)__bfloat16_as_ushort(hl) << 16);
}

__device__ __forceinline__ __nv_bfloat162 split_hi2(float a, float b) {
    return __halves2bfloat162(__float2bfloat16(a), __float2bfloat16(b));
}
__device__ __forceinline__ __nv_bfloat162 split_lo2(float a, float b) {
    __nv_bfloat16 ha = __float2bfloat16(a), hb = __float2bfloat16(b);
    return __halves2bfloat162(__float2bfloat16(a - __bfloat162float(ha)),
                              __float2bfloat16(b - __bfloat162float(hb)));
}

// ---------------- fused routing (single CTA) ---------------------------------
__global__ __launch_bounds__(1024) void k_route(const int* __restrict__ routing) {
    __shared__ int sc[EE];
    __shared__ int so[EE];
    __shared__ int scur[EE];
    int tid = threadIdx.x;
    if (tid < EE) { sc[tid] = 0; scur[tid] = 0; }
    __syncthreads();
    for (int i = tid; i < TKN; i += 1024) atomicAdd(&sc[routing[i]], 1);
    __syncthreads();
    if (tid == 0) {
        int off = 0, nt = 0;
        for (int e = 0; e < EE; e++) {
            so[e] = off; g_offsets[e] = off;
            for (int r = 0; r < sc[e]; r += TM) {
                g_tile_expert[nt] = e;
                g_tile_row[nt]    = off + r;
                nt++;
            }
            off += sc[e];
        }
        g_offsets[EE] = off;
        g_num_tiles = nt;
    }
    __syncthreads();
    for (int i = tid; i < TKN; i += 1024) {
        int e = routing[i];
        int pos = so[e] + atomicAdd(&scur[e], 1);
        g_slot_token[pos] = i >> 1;           // KK=2
        g_tok_slot[i]     = pos;
    }
}

// ---------------- conversions ------------------------------------------------
__global__ __launch_bounds__(256) void k_conv_x(const float* __restrict__ x) {
    int slot = blockIdx.x;
    int tok  = g_slot_token[slot];
    int j    = threadIdx.x;                 // 256 threads x 4 floats = 1024 = HH
    float4 v = ((const float4*)(x + (size_t)tok * HH))[j];
    __nv_bfloat162* dh = (__nv_bfloat162*)(g_xg_hi + (size_t)slot * HH) + 2 * j;
    __nv_bfloat162* dl = (__nv_bfloat162*)(g_xg_lo + (size_t)slot * HH) + 2 * j;
    dh[0] = split_hi2(v.x, v.y); dh[1] = split_hi2(v.z, v.w);
    dl[0] = split_lo2(v.x, v.y); dl[1] = split_lo2(v.z, v.w);
}

// w13 [E][H][2I] -> g_w13i [E][2I][H] (gate/up interleaved), split hi/lo.
// 64x64 tiles, float2 loads, bf16x2 stores.
__global__ __launch_bounds__(256) void k_tconv13(const float* __restrict__ w13) {
    __shared__ float smg[64][65];
    __shared__ float smu[64][65];
    int e  = blockIdx.z;
    int i0 = blockIdx.x * 64;    // intermediate block
    int h0 = blockIdx.y * 64;    // hidden block
    int t  = threadIdx.x;
    int lw = t >> 5, l = t & 31;
    const float* s = w13 + (size_t)e * HH * (2 * II);
#pragma unroll
    for (int p = 0; p < 8; p++) {
        int h = lw + p * 8;
        const float* rp = s + (size_t)(h0 + h) * (2 * II);
        float2 vg = *(const float2*)(rp + i0 + 2 * l);
        float2 vu = *(const float2*)(rp + II + i0 + 2 * l);
        smg[h][2 * l] = vg.x; smg[h][2 * l + 1] = vg.y;
        smu[h][2 * l] = vu.x; smu[h][2 * l + 1] = vu.y;
    }
    __syncthreads();
    size_t db = (size_t)e * 2 * II * HH;
#pragma unroll
    for (int p = 0; p < 8; p++) {
        int i = lw + p * 8;
        float g0 = smg[2 * l][i], g1 = smg[2 * l + 1][i];
        float u0 = smu[2 * l][i], u1 = smu[2 * l + 1][i];
        size_t og = db + (size_t)(2 * (i0 + i))     * HH + h0 + 2 * l;
        size_t ou = db + (size_t)(2 * (i0 + i) + 1) * HH + h0 + 2 * l;
        *(__nv_bfloat162*)(g_w13i_hi + og) = split_hi2(g0, g1);
        *(__nv_bfloat162*)(g_w13i_lo + og) = split_lo2(g0, g1);
        *(__nv_bfloat162*)(g_w13i_hi + ou) = split_hi2(u0, u1);
        *(__nv_bfloat162*)(g_w13i_lo + ou) = split_lo2(u0, u1);
    }
}

// w2 [E][I][H] -> g_w2t [E][H][I], split hi/lo. 64x64 tiles.
__global__ __launch_bounds__(256) void k_tconv2(const float* __restrict__ w2) {
    __shared__ float sm[64][65];
    int e  = blockIdx.z;
    int i0 = blockIdx.x * 64;    // I block
    int h0 = blockIdx.y * 64;    // H block
    int t  = threadIdx.x;
    int lw = t >> 5, l = t & 31;
    const float* s = w2 + (size_t)e * II * HH;
#pragma unroll
    for (int p = 0; p < 8; p++) {
        int i = lw + p * 8;
        float2 v = *(const float2*)(s + (size_t)(i0 + i) * HH + h0 + 2 * l);
        sm[i][2 * l] = v.x; sm[i][2 * l + 1] = v.y;
    }
    __syncthreads();
    size_t db = (size_t)e * HH * II;
#pragma unroll
    for (int p = 0; p < 8; p++) {
        int h = lw + p * 8;
        float v0 = sm[2 * l][h], v1 = sm[2 * l + 1][h];
        size_t o = db + (size_t)(h0 + h) * II + i0 + 2 * l;
        *(__nv_bfloat162*)(g_w2t_hi + o) = split_hi2(v0, v1);
        *(__nv_bfloat162*)(g_w2t_lo + o) = split_lo2(v0, v1);
    }
}

// ---------------- tensor-core grouped GEMM (wave-launched) -------------------
// smem layout per stage: 4 planes (Ah, Al, Bh, Bl), each 128 rows x 64 B,
// chunk-swizzled: addr(row, chunk) = row*64 + (chunk ^ ((row>>1)&3))*16
// MODE 1: h = silu(X@W1g)*(X@W1u)  [A=g_xg, B=g_w13i(interleaved), K=HH]
// MODE 2: y = h @ W2               [A=g_h,  B=g_w2t,               K=II]
template<int MODE>
__global__ __launch_bounds__(256, 2) void k_mma() {
    constexpr int KDIM = (MODE == 1) ? HH : II;
    constexpr int NK   = KDIM / BK;
    constexpr size_t STRD = (MODE == 1) ? (size_t)HH * 2 : (size_t)II * 2;

    int tile = blockIdx.y;
    if (tile >= g_num_tiles) return;
    int e = g_tile_expert[tile], row0 = g_tile_row[tile], n_end = g_offsets[e + 1];
    int n0 = blockIdx.x * 128;
    int tid = threadIdx.x, wid = tid >> 5, lane = tid & 31;
    int wm = wid & 3, wn = wid >> 2;       // 4 x 2 warp grid
    int m0 = wm * 32, n0w = wn * 64;

    extern __shared__ char sm[];
    uint32_t sb = smem_u32(sm);

    const char *pAh, *pAl, *pBh, *pBl;
    if (MODE == 1) {
        pAh = (const char*)(g_xg_hi + (size_t)row0 * HH);
        pAl = (const char*)(g_xg_lo + (size_t)row0 * HH);
        size_t wb = (size_t)e * 2 * II * HH + (size_t)n0 * HH;
        pBh = (const char*)(g_w13i_hi + wb);
        pBl = (const char*)(g_w13i_lo + wb);
    } else {
        pAh = (const char*)(g_h_hi + (size_t)row0 * II);
        pAl = (const char*)(g_h_lo + (size_t)row0 * II);
        size_t wb = (size_t)e * HH * II + (size_t)n0 * II;
        pBh = (const char*)(g_w2t_hi + wb);
        pBl = (const char*)(g_w2t_lo + wb);
    }

    // per-thread auto-advancing load pointers (8): 4 planes x 2 row-groups
    int lrow = tid >> 2, lc16 = tid & 3;
    size_t tho = (size_t)lrow * STRD + (size_t)lc16 * 16;
    const char* gp[8];
    gp[0] = pAh + tho; gp[1] = gp[0] + 64 * STRD;
    gp[2] = pAl + tho; gp[3] = gp[2] + 64 * STRD;
    gp[4] = pBh + tho; gp[5] = gp[4] + 64 * STRD;
    gp[6] = pBl + tho; gp[7] = gp[6] + 64 * STRD;
    // swizzled smem destination offset (row+64 keeps the same swizzle)
    uint32_t dof = (uint32_t)lrow * 64u + (uint32_t)((lc16 ^ ((lrow >> 1) & 3)) * 16);

    auto load_stage = [&](int s) {
        uint32_t dstS = sb + (uint32_t)s * STAGE + dof;
#pragma unroll
        for (int p = 0; p < 4; p++) {
            uint32_t d0 = dstS + p * PLANE;
            asm volatile("cp.async.cg.shared.global [%0], [%1], 16;" :: "r"(d0), "l"(gp[2 * p]));
            asm volatile("cp.async.cg.shared.global [%0], [%1], 16;" :: "r"(d0 + 64 * 64), "l"(gp[2 * p + 1]));
            gp[2 * p]     += 64;
            gp[2 * p + 1] += 64;
        }
        asm volatile("cp.async.commit_group;");
    };

    // fragment address components (swizzle invariant under +16 rows)
    int arow = m0 + (lane & 15);
    int brow = (lane & 7) + ((lane >> 4) << 3);
    uint32_t aswz[2], bswz[2];
#pragma unroll
    for (int sub = 0; sub < 2; sub++) {
        int ca = (lane >> 4) + sub * 2;
        int cb = ((lane >> 3) & 1) + sub * 2;
        aswz[sub] = (uint32_t)arow * 64u + (uint32_t)((ca ^ ((arow >> 1) & 3)) * 16);
        bswz[sub] = (uint32_t)(n0w + brow) * 64u + (uint32_t)((cb ^ ((brow >> 1) & 3)) * 16);
    }

    float acc[16][4];
#pragma unroll
    for (int i = 0; i < 16; i++)
#pragma unroll
        for (int j = 0; j < 4; j++) acc[i][j] = 0.f;

    load_stage(0);
    load_stage(1);

    int cs = 0, fs = 2;
    for (int ks = 0; ks < NK; ks++) {
        if (ks == NK - 1) asm volatile("cp.async.wait_group 0;");
        else              asm volatile("cp.async.wait_group 1;");
        __syncthreads();
        if (ks + 2 < NK) { load_stage(fs); fs = (fs == NSTG - 1) ? 0 : fs + 1; }

        uint32_t base = sb + (uint32_t)cs * STAGE;
        cs = (cs == NSTG - 1) ? 0 : cs + 1;
#pragma unroll
        for (int sub = 0; sub < 2; sub++) {
            uint32_t a0 = base + aswz[sub];
            uint32_t ah[2][4], al[2][4];
            ldmx4(ah[0], a0);
            ldmx4(ah[1], a0 + 16 * 64);
            ldmx4(al[0], a0 + PLANE);
            ldmx4(al[1], a0 + PLANE + 16 * 64);
            uint32_t b0 = base + 2 * PLANE + bswz[sub];
#pragma unroll
            for (int jj = 0; jj < 4; jj++) {
                uint32_t bh[4], bl[4];
                ldmx4(bh, b0 + jj * 1024);
                ldmx4(bl, b0 + PLANE + jj * 1024);
#pragma unroll
                for (int i = 0; i < 2; i++) {
                    mma16816(acc[i * 8 + jj * 2 + 0], ah[i], bh + 0);
                    mma16816(acc[i * 8 + jj * 2 + 1], ah[i], bh + 2);
                }
#pragma unroll
                for (int i = 0; i < 2; i++) {
                    mma16816(acc[i * 8 + jj * 2 + 0], ah[i], bl + 0);
                    mma16816(acc[i * 8 + jj * 2 + 1], ah[i], bl + 2);
                }
#pragma unroll
                for (int i = 0; i < 2; i++) {
                    mma16816(acc[i * 8 + jj * 2 + 0], al[i], bh + 0);
                    mma16816(acc[i * 8 + jj * 2 + 1], al[i], bh + 2);
                }
            }
        }
    }

    // ---------------- epilogue ----------------
    if (MODE == 1) {
        // stage packed (hi,lo) h values in smem (68-word padded rows), then
        // write out coalesced.
        __syncthreads();
        uint32_t* st = (uint32_t*)sm;
        int q = lane & 3;
        int rl = m0 + (lane >> 2);
#pragma unroll
        for (int i = 0; i < 2; i++) {
#pragma unroll
            for (int j = 0; j < 8; j++) {
                const float* c = acc[i * 8 + j];
                int hcl = ((n0w + j * 8) >> 1) + q;
                st[(rl + i * 16)     * 68 + hcl] = pack_h(c[0], c[1]);
                st[(rl + i * 16 + 8) * 68 + hcl] = pack_h(c[2], c[3]);
            }
        }
        __syncthreads();
        int hb = n0 >> 1;
#pragma unroll
        for (int pass = 0; pass < 8; pass++) {
            int r  = pass * 16 + (tid >> 4);
            int c4 = (tid & 15) * 4;
            int grow = row0 + r;
            if (grow < n_end) {
                uint32_t w0 = st[r * 68 + c4 + 0], w1 = st[r * 68 + c4 + 1];
                uint32_t w2 = st[r * 68 + c4 + 2], w3 = st[r * 68 + c4 + 3];
                uint32_t hi0 = (w0 & 0xffffu) | (w1 << 16);
                uint32_t hi1 = (w2 & 0xffffu) | (w3 << 16);
                uint32_t lo0 = (w0 >> 16) | (w1 & 0xffff0000u);
                uint32_t lo1 = (w2 >> 16) | (w3 & 0xffff0000u);
                size_t off = (size_t)grow * II + hb + c4;
                *(uint2*)(g_h_hi + off) = make_uint2(hi0, hi1);
                *(uint2*)(g_h_lo + off) = make_uint2(lo0, lo1);
            }
        }
    } else {
        // plain coalesced-ish float2 stores to y scratch; no atomics
        int rbase = row0 + m0 + (lane >> 2);
        int q     = lane & 3;
#pragma unroll
        for (int i = 0; i < 2; i++) {
            int ra = rbase + i * 16;
#pragma unroll
            for (int j = 0; j < 8; j++) {
                const float* c = acc[i * 8 + j];
                int col = n0 + n0w + j * 8 + 2 * q;
                if (ra < n_end)
                    *(float2*)(g_y + (size_t)ra * HH + col) = make_float2(c[0], c[1]);
                if (ra + 8 < n_end)
                    *(float2*)(g_y + (size_t)(ra + 8) * HH + col) = make_float2(c[2], c[3]);
            }
        }
    }
}

// ---------------- combine: out[t] = sum_k rw[t,k] * y[slot(t,k)] -------------
__global__ __launch_bounds__(256) void k_combine(const float* __restrict__ rw,
                                                 float* __restrict__ out) {
    size_t i = (size_t)blockIdx.x * blockDim.x + threadIdx.x;
    if (i >= (size_t)TT * HH) return;
    int t = (int)(i >> 10);
    int h = (int)(i & 1023);
    int s0 = g_tok_slot[2 * t], s1 = g_tok_slot[2 * t + 1];
    out[i] = rw[2 * t] * g_y[(size_t)s0 * HH + h] + rw[2 * t + 1] * g_y[(size_t)s1 * HH + h];
}

// ---------------- launch -----------------------------------------------------
extern "C" void kernel_launch(void* const* d_in, const int* in_sizes, int n_in,
                              void* d_out, int out_size) {
    const float* x        = (const float*)d_in[0];   // [T,H]
    const int*   routing  = (const int*)  d_in[1];   // [T,K]
    const float* rweights = (const float*)d_in[2];   // [T,K]
    const float* w13      = (const float*)d_in[3];   // [E,H,2I]
    const float* w2       = (const float*)d_in[4];   // [E,I,H]
    float*       out      = (float*)d_out;           // [T,H]

    cudaFuncSetAttribute(k_mma<1>, cudaFuncAttributeMaxDynamicSharedMemorySize, SMEM_BYTES);
    cudaFuncSetAttribute(k_mma<2>, cudaFuncAttributeMaxDynamicSharedMemorySize, SMEM_BYTES);

    // order chosen so launch index 3 (ncu capture slot) is k_mma<1>
    k_route<<<1, 1024>>>(routing);                                 // 0
    k_conv_x<<<TKN, 256>>>(x);                                     // 1
    {
        dim3 g(II / 64, HH / 64, EE);    // 44 x 16 x 8
        k_tconv13<<<g, 256>>>(w13);                                // 2
    }
    k_mma<1><<<dim3(2 * II / 128, NT_MAX), 256, SMEM_BYTES>>>();   // 3
    {
        dim3 g(II / 64, HH / 64, EE);    // 44 x 16 x 8
        k_tconv2<<<g, 256>>>(w2);                                  // 4
    }
    k_mma<2><<<dim3(HH / 128, NT_MAX), 256, SMEM_BYTES>>>();       // 5
    {
        size_t n = (size_t)TT * HH;
        k_combine<<<(unsigned)((n + 255) / 256), 256>>>(rweights, out);  // 6
    }
}

// round 13
// speedup vs baseline: 1.0149x; 1.0149x over previous
#include <cuda_runtime.h>
#include <cuda_bf16.h>
#include <math.h>
#include <stdint.h>

// ---------------- problem constants ------------------------------------------
#define TT   8192
#define KK   2
#define HH   1024
#define II   2816
#define EE   8
#define TKN  (TT*KK)          // 16384 assignments
#define TM   128              // rows per GEMM tile
#define NT_MAX (TKN/TM + EE)  // 136 row tiles max
#define PAD  256

// GEMM tiling: swizzled smem, no padding
#define BK    32
#define PLANE (128*64)        // 8192 B per operand plane (128 rows x 64 B)
#define STAGE (4*PLANE)       // 32768 B per pipeline stage
#define NSTG  3
#define SMEM_BYTES (NSTG*STAGE)  // 98304 B

// fused-aux grid split for MODE 1 (x dimension)
#define NX_MMA1   44          // 2*II/128 n-tiles
#define NX_TCONV  42          // 42*136 = 5712 >= 5632 tconv2 tiles
#define NX_ZERO   61          // 61*136 = 8296 >= 8192 zero chunks
#define NX_TOTAL  (NX_MMA1 + NX_TCONV + NX_ZERO)   // 147
#define N_TCONV2  (EE * (HH/64) * (II/64))          // 5632
#define N_ZERO    ((TT*HH)/1024)                    // 8192 chunks of 1024 floats

// ---------------- device scratch ---------------------------------------------
__device__ int   g_offsets[EE + 1];
__device__ int   g_slot_token[TKN + PAD];
__device__ float g_slot_weight[TKN + PAD];
__device__ int   g_tile_expert[NT_MAX];
__device__ int   g_tile_row[NT_MAX];
__device__ int   g_num_tiles;

__device__ __align__(256) __nv_bfloat16 g_xg_hi[(size_t)(TKN + PAD) * HH];
__device__ __align__(256) __nv_bfloat16 g_xg_lo[(size_t)(TKN + PAD) * HH];
// w13 transposed, gate/up interleaved: n=2i -> gate col i, n=2i+1 -> up col i
__device__ __align__(256) __nv_bfloat16 g_w13i_hi[(size_t)EE * 2 * II * HH];
__device__ __align__(256) __nv_bfloat16 g_w13i_lo[(size_t)EE * 2 * II * HH];
__device__ __align__(256) __nv_bfloat16 g_w2t_hi[(size_t)EE * HH * II];
__device__ __align__(256) __nv_bfloat16 g_w2t_lo[(size_t)EE * HH * II];
__device__ __align__(256) __nv_bfloat16 g_h_hi[(size_t)(TKN + PAD) * II];
__device__ __align__(256) __nv_bfloat16 g_h_lo[(size_t)(TKN + PAD) * II];

// ---------------- helpers ----------------------------------------------------
__device__ __forceinline__ uint32_t smem_u32(const void* p) {
    uint32_t a;
    asm("{ .reg .u64 t; cvta.to.shared.u64 t, %1; cvt.u32.u64 %0, t; }" : "=r"(a) : "l"(p));
    return a;
}

__device__ __forceinline__ void ldmx4(uint32_t* r, uint32_t addr) {
    asm volatile("ldmatrix.sync.aligned.m8n8.x4.shared.b16 {%0,%1,%2,%3}, [%4];"
        : "=r"(r[0]), "=r"(r[1]), "=r"(r[2]), "=r"(r[3]) : "r"(addr));
}

__device__ __forceinline__ void mma16816(float* d, const uint32_t* a, const uint32_t* b) {
    asm volatile("mma.sync.aligned.m16n8k16.row.col.f32.bf16.bf16.f32 "
        "{%0,%1,%2,%3}, {%4,%5,%6,%7}, {%8,%9}, {%0,%1,%2,%3};"
        : "+f"(d[0]), "+f"(d[1]), "+f"(d[2]), "+f"(d[3])
        : "r"(a[0]), "r"(a[1]), "r"(a[2]), "r"(a[3]), "r"(b[0]), "r"(b[1]));
}

__device__ __forceinline__ uint32_t pack_h(float g, float u) {
    float h = u * (g / (1.0f + __expf(-g)));
    __nv_bfloat16 hh = __float2bfloat16(h);
    __nv_bfloat16 hl = __float2bfloat16(h - __bfloat162float(hh));
    return (uint32_t)__bfloat16_as_ushort(hh) | ((uint32_t)__bfloat16_as_ushort(hl) << 16);
}

__device__ __forceinline__ __nv_bfloat162 split_hi2(float a, float b) {
    return __halves2bfloat162(__float2bfloat16(a), __float2bfloat16(b));
}
__device__ __forceinline__ __nv_bfloat162 split_lo2(float a, float b) {
    __nv_bfloat16 ha = __float2bfloat16(a), hb = __float2bfloat16(b);
    return __halves2bfloat162(__float2bfloat16(a - __bfloat162float(ha)),
                              __float2bfloat16(b - __bfloat162float(hb)));
}

// ---------------- fused routing (single CTA) ---------------------------------
__global__ __launch_bounds__(1024) void k_route(const int* __restrict__ routing,
                                                const float* __restrict__ rweights) {
    __shared__ int sc[EE];
    __shared__ int so[EE];
    __shared__ int scur[EE];
    int tid = threadIdx.x;
    if (tid < EE) { sc[tid] = 0; scur[tid] = 0; }
    __syncthreads();
    for (int i = tid; i < TKN; i += 1024) atomicAdd(&sc[routing[i]], 1);
    __syncthreads();
    if (tid == 0) {
        int off = 0, nt = 0;
        for (int e = 0; e < EE; e++) {
            so[e] = off; g_offsets[e] = off;
            for (int r = 0; r < sc[e]; r += TM) {
                g_tile_expert[nt] = e;
                g_tile_row[nt]    = off + r;
                nt++;
            }
            off += sc[e];
        }
        g_offsets[EE] = off;
        g_num_tiles = nt;
    }
    __syncthreads();
    for (int i = tid; i < TKN; i += 1024) {
        int e = routing[i];
        int pos = so[e] + atomicAdd(&scur[e], 1);
        g_slot_token[pos]  = i >> 1;           // KK=2
        g_slot_weight[pos] = rweights[i];
    }
}

// ---------------- conversions ------------------------------------------------
__global__ __launch_bounds__(256) void k_conv_x(const float* __restrict__ x) {
    int slot = blockIdx.x;
    int tok  = g_slot_token[slot];
    int j    = threadIdx.x;                 // 256 threads x 4 floats = 1024 = HH
    float4 v = ((const float4*)(x + (size_t)tok * HH))[j];
    __nv_bfloat162* dh = (__nv_bfloat162*)(g_xg_hi + (size_t)slot * HH) + 2 * j;
    __nv_bfloat162* dl = (__nv_bfloat162*)(g_xg_lo + (size_t)slot * HH) + 2 * j;
    dh[0] = split_hi2(v.x, v.y); dh[1] = split_hi2(v.z, v.w);
    dl[0] = split_lo2(v.x, v.y); dl[1] = split_lo2(v.z, v.w);
}

// w13 [E][H][2I] -> g_w13i [E][2I][H] (gate/up interleaved), split hi/lo.
// 64x64 tiles, float2 loads, bf16x2 stores.
__global__ __launch_bounds__(256) void k_tconv13(const float* __restrict__ w13) {
    __shared__ float smg[64][65];
    __shared__ float smu[64][65];
    int e  = blockIdx.z;
    int i0 = blockIdx.x * 64;    // intermediate block
    int h0 = blockIdx.y * 64;    // hidden block
    int t  = threadIdx.x;
    int lw = t >> 5, l = t & 31;
    const float* s = w13 + (size_t)e * HH * (2 * II);
#pragma unroll
    for (int p = 0; p < 8; p++) {
        int h = lw + p * 8;
        const float* rp = s + (size_t)(h0 + h) * (2 * II);
        float2 vg = *(const float2*)(rp + i0 + 2 * l);
        float2 vu = *(const float2*)(rp + II + i0 + 2 * l);
        smg[h][2 * l] = vg.x; smg[h][2 * l + 1] = vg.y;
        smu[h][2 * l] = vu.x; smu[h][2 * l + 1] = vu.y;
    }
    __syncthreads();
    size_t db = (size_t)e * 2 * II * HH;
#pragma unroll
    for (int p = 0; p < 8; p++) {
        int i = lw + p * 8;
        float g0 = smg[2 * l][i], g1 = smg[2 * l + 1][i];
        float u0 = smu[2 * l][i], u1 = smu[2 * l + 1][i];
        size_t og = db + (size_t)(2 * (i0 + i))     * HH + h0 + 2 * l;
        size_t ou = db + (size_t)(2 * (i0 + i) + 1) * HH + h0 + 2 * l;
        *(__nv_bfloat162*)(g_w13i_hi + og) = split_hi2(g0, g1);
        *(__nv_bfloat162*)(g_w13i_lo + og) = split_lo2(g0, g1);
        *(__nv_bfloat162*)(g_w13i_hi + ou) = split_hi2(u0, u1);
        *(__nv_bfloat162*)(g_w13i_lo + ou) = split_lo2(u0, u1);
    }
}

// ---------------- tensor-core grouped GEMM (wave-launched) -------------------
// smem layout per stage: 4 planes (Ah, Al, Bh, Bl), each 128 rows x 64 B,
// chunk-swizzled: addr(row, chunk) = row*64 + (chunk ^ ((row>>1)&3))*16
// MODE 1: h = silu(X@W1g)*(X@W1u)  [A=g_xg, B=g_w13i(interleaved), K=HH]
//         PLUS fused aux blocks (x >= NX_MMA1): w2 transpose tiles + out zeroing,
//         interleaved into the grid so their DRAM work overlaps mma tensor work.
// MODE 2: out[tok] += w*(h@W2)     [A=g_h,  B=g_w2t,               K=II]
template<int MODE>
__global__ __launch_bounds__(256, 2) void k_mma(float* __restrict__ out,
                                                const float* __restrict__ w2) {
    constexpr int KDIM = (MODE == 1) ? HH : II;
    constexpr int NK   = KDIM / BK;
    constexpr size_t STRD = (MODE == 1) ? (size_t)HH * 2 : (size_t)II * 2;

    extern __shared__ char sm[];

    int tid = threadIdx.x;

    // ---------------- fused aux paths (MODE 1 only) ----------------
    if (MODE == 1 && blockIdx.x >= NX_MMA1) {
        int xa = blockIdx.x - NX_MMA1;
        if (xa < NX_TCONV) {
            // ---- w2 [E][I][H] -> g_w2t [E][H][I], split hi/lo (64x64 tile) ----
            int idx = xa + NX_TCONV * blockIdx.y;
            if (idx < N_TCONV2) {
                float* smt = (float*)sm;           // 64 x 65 floats in dynamic smem
                int e  = idx / ((HH / 64) * (II / 64));     // 704 tiles per expert
                int r  = idx - e * ((HH / 64) * (II / 64));
                int h0 = (r / (II / 64)) * 64;
                int i0 = (r % (II / 64)) * 64;
                int lw = tid >> 5, l = tid & 31;
                const float* s = w2 + (size_t)e * II * HH;
#pragma unroll
                for (int p = 0; p < 8; p++) {
                    int i = lw + p * 8;
                    float2 v = *(const float2*)(s + (size_t)(i0 + i) * HH + h0 + 2 * l);
                    smt[i * 65 + 2 * l]     = v.x;
                    smt[i * 65 + 2 * l + 1] = v.y;
                }
                __syncthreads();
                size_t db = (size_t)e * HH * II;
#pragma unroll
                for (int p = 0; p < 8; p++) {
                    int h = lw + p * 8;
                    float v0 = smt[(2 * l) * 65 + h], v1 = smt[(2 * l + 1) * 65 + h];
                    size_t o = db + (size_t)(h0 + h) * II + i0 + 2 * l;
                    *(__nv_bfloat162*)(g_w2t_hi + o) = split_hi2(v0, v1);
                    *(__nv_bfloat162*)(g_w2t_lo + o) = split_lo2(v0, v1);
                }
            }
        } else {
            // ---- zero output chunks (1024 floats each) ----
            int z = (xa - NX_TCONV) + NX_ZERO * blockIdx.y;
            if (z < N_ZERO)
                ((float4*)out)[(size_t)z * 256 + tid] = make_float4(0.f, 0.f, 0.f, 0.f);
        }
        return;
    }

    // ---------------- GEMM path ----------------
    int tile = blockIdx.y;
    if (tile >= g_num_tiles) return;
    int e = g_tile_expert[tile], row0 = g_tile_row[tile], n_end = g_offsets[e + 1];
    int n0 = blockIdx.x * 128;
    int wid = tid >> 5, lane = tid & 31;
    int wm = wid & 3, wn = wid >> 2;       // 4 x 2 warp grid
    int m0 = wm * 32, n0w = wn * 64;

    uint32_t sb = smem_u32(sm);

    const char *pAh, *pAl, *pBh, *pBl;
    if (MODE == 1) {
        pAh = (const char*)(g_xg_hi + (size_t)row0 * HH);
        pAl = (const char*)(g_xg_lo + (size_t)row0 * HH);
        size_t wb = (size_t)e * 2 * II * HH + (size_t)n0 * HH;
        pBh = (const char*)(g_w13i_hi + wb);
        pBl = (const char*)(g_w13i_lo + wb);
    } else {
        pAh = (const char*)(g_h_hi + (size_t)row0 * II);
        pAl = (const char*)(g_h_lo + (size_t)row0 * II);
        size_t wb = (size_t)e * HH * II + (size_t)n0 * II;
        pBh = (const char*)(g_w2t_hi + wb);
        pBl = (const char*)(g_w2t_lo + wb);
    }

    // per-thread auto-advancing load pointers (8): 4 planes x 2 row-groups
    int lrow = tid >> 2, lc16 = tid & 3;
    size_t tho = (size_t)lrow * STRD + (size_t)lc16 * 16;
    const char* gp[8];
    gp[0] = pAh + tho; gp[1] = gp[0] + 64 * STRD;
    gp[2] = pAl + tho; gp[3] = gp[2] + 64 * STRD;
    gp[4] = pBh + tho; gp[5] = gp[4] + 64 * STRD;
    gp[6] = pBl + tho; gp[7] = gp[6] + 64 * STRD;
    // swizzled smem destination offset (row+64 keeps the same swizzle)
    uint32_t dof = (uint32_t)lrow * 64u + (uint32_t)((lc16 ^ ((lrow >> 1) & 3)) * 16);

    auto load_stage = [&](int s) {
        uint32_t dstS = sb + (uint32_t)s * STAGE + dof;
#pragma unroll
        for (int p = 0; p < 4; p++) {
            uint32_t d0 = dstS + p * PLANE;
            asm volatile("cp.async.cg.shared.global [%0], [%1], 16;" :: "r"(d0), "l"(gp[2 * p]));
            asm volatile("cp.async.cg.shared.global [%0], [%1], 16;" :: "r"(d0 + 64 * 64), "l"(gp[2 * p + 1]));
            gp[2 * p]     += 64;
            gp[2 * p + 1] += 64;
        }
        asm volatile("cp.async.commit_group;");
    };

    // fragment address components (swizzle invariant under +16 rows)
    int arow = m0 + (lane & 15);
    int brow = (lane & 7) + ((lane >> 4) << 3);
    uint32_t aswz[2], bswz[2];
#pragma unroll
    for (int sub = 0; sub < 2; sub++) {
        int ca = (lane >> 4) + sub * 2;
        int cb = ((lane >> 3) & 1) + sub * 2;
        aswz[sub] = (uint32_t)arow * 64u + (uint32_t)((ca ^ ((arow >> 1) & 3)) * 16);
        bswz[sub] = (uint32_t)(n0w + brow) * 64u + (uint32_t)((cb ^ ((brow >> 1) & 3)) * 16);
    }

    float acc[16][4];
#pragma unroll
    for (int i = 0; i < 16; i++)
#pragma unroll
        for (int j = 0; j < 4; j++) acc[i][j] = 0.f;

    load_stage(0);
    load_stage(1);

    int cs = 0, fs = 2;
    for (int ks = 0; ks < NK; ks++) {
        if (ks == NK - 1) asm volatile("cp.async.wait_group 0;");
        else              asm volatile("cp.async.wait_group 1;");
        __syncthreads();
        if (ks + 2 < NK) { load_stage(fs); fs = (fs == NSTG - 1) ? 0 : fs + 1; }

        uint32_t base = sb + (uint32_t)cs * STAGE;
        cs = (cs == NSTG - 1) ? 0 : cs + 1;
#pragma unroll
        for (int sub = 0; sub < 2; sub++) {
            uint32_t a0 = base + aswz[sub];
            uint32_t ah[2][4], al[2][4];
            ldmx4(ah[0], a0);
            ldmx4(ah[1], a0 + 16 * 64);
            ldmx4(al[0], a0 + PLANE);
            ldmx4(al[1], a0 + PLANE + 16 * 64);
            uint32_t b0 = base + 2 * PLANE + bswz[sub];
#pragma unroll
            for (int jj = 0; jj < 4; jj++) {
                uint32_t bh[4], bl[4];
                ldmx4(bh, b0 + jj * 1024);
                ldmx4(bl, b0 + PLANE + jj * 1024);
#pragma unroll
                for (int i = 0; i < 2; i++) {
                    mma16816(acc[i * 8 + jj * 2 + 0], ah[i], bh + 0);
                    mma16816(acc[i * 8 + jj * 2 + 1], ah[i], bh + 2);
                }
#pragma unroll
                for (int i = 0; i < 2; i++) {
                    mma16816(acc[i * 8 + jj * 2 + 0], ah[i], bl + 0);
                    mma16816(acc[i * 8 + jj * 2 + 1], ah[i], bl + 2);
                }
#pragma unroll
                for (int i = 0; i < 2; i++) {
                    mma16816(acc[i * 8 + jj * 2 + 0], al[i], bh + 0);
                    mma16816(acc[i * 8 + jj * 2 + 1], al[i], bh + 2);
                }
            }
        }
    }

    // ---------------- epilogue ----------------
    if (MODE == 1) {
        // stage packed (hi,lo) h values in smem (68-word padded rows), then
        // write out coalesced.
        __syncthreads();
        uint32_t* st = (uint32_t*)sm;
        int q = lane & 3;
        int rl = m0 + (lane >> 2);
#pragma unroll
        for (int i = 0; i < 2; i++) {
#pragma unroll
            for (int j = 0; j < 8; j++) {
                const float* c = acc[i * 8 + j];
                int hcl = ((n0w + j * 8) >> 1) + q;
                st[(rl + i * 16)     * 68 + hcl] = pack_h(c[0], c[1]);
                st[(rl + i * 16 + 8) * 68 + hcl] = pack_h(c[2], c[3]);
            }
        }
        __syncthreads();
        int hb = n0 >> 1;
#pragma unroll
        for (int pass = 0; pass < 8; pass++) {
            int r  = pass * 16 + (tid >> 4);
            int c4 = (tid & 15) * 4;
            int grow = row0 + r;
            if (grow < n_end) {
                uint32_t w0 = st[r * 68 + c4 + 0], w1 = st[r * 68 + c4 + 1];
                uint32_t w2v = st[r * 68 + c4 + 2], w3 = st[r * 68 + c4 + 3];
                uint32_t hi0 = (w0 & 0xffffu) | (w1 << 16);
                uint32_t hi1 = (w2v & 0xffffu) | (w3 << 16);
                uint32_t lo0 = (w0 >> 16) | (w1 & 0xffff0000u);
                uint32_t lo1 = (w2v >> 16) | (w3 & 0xffff0000u);
                size_t off = (size_t)grow * II + hb + c4;
                *(uint2*)(g_h_hi + off) = make_uint2(hi0, hi1);
                *(uint2*)(g_h_lo + off) = make_uint2(lo0, lo1);
            }
        }
    } else {
        // fused combine: out[tok] += w * acc (2 commutative fp32 adds/element)
        int rbase = row0 + m0 + (lane >> 2);
        int q     = lane & 3;
#pragma unroll
        for (int i = 0; i < 2; i++) {
            int ra = rbase + i * 16;
            bool ok0 = (ra < n_end), ok1 = (ra + 8 < n_end);
            int   t0 = ok0 ? g_slot_token[ra]     : 0;
            int   t1 = ok1 ? g_slot_token[ra + 8] : 0;
            float w0 = ok0 ? g_slot_weight[ra]     : 0.f;
            float w1 = ok1 ? g_slot_weight[ra + 8] : 0.f;
#pragma unroll
            for (int j = 0; j < 8; j++) {
                const float* c = acc[i * 8 + j];
                int col = n0 + n0w + j * 8 + 2 * q;
                if (ok0) {
                    atomicAdd(out + (size_t)t0 * HH + col,     w0 * c[0]);
                    atomicAdd(out + (size_t)t0 * HH + col + 1, w0 * c[1]);
                }
                if (ok1) {
                    atomicAdd(out + (size_t)t1 * HH + col,     w1 * c[2]);
                    atomicAdd(out + (size_t)t1 * HH + col + 1, w1 * c[3]);
                }
            }
        }
    }
}

// ---------------- launch -----------------------------------------------------
extern "C" void kernel_launch(void* const* d_in, const int* in_sizes, int n_in,
                              void* d_out, int out_size) {
    const float* x        = (const float*)d_in[0];   // [T,H]
    const int*   routing  = (const int*)  d_in[1];   // [T,K]
    const float* rweights = (const float*)d_in[2];   // [T,K]
    const float* w13      = (const float*)d_in[3];   // [E,H,2I]
    const float* w2       = (const float*)d_in[4];   // [E,I,H]
    float*       out      = (float*)d_out;           // [T,H]

    cudaFuncSetAttribute(k_mma<1>, cudaFuncAttributeMaxDynamicSharedMemorySize, SMEM_BYTES);
    cudaFuncSetAttribute(k_mma<2>, cudaFuncAttributeMaxDynamicSharedMemorySize, SMEM_BYTES);

    // order chosen so launch index 3 (ncu capture slot) is the fused k_mma<1>
    k_route<<<1, 1024>>>(routing, rweights);                       // 0
    k_conv_x<<<TKN, 256>>>(x);                                     // 1
    {
        dim3 g(II / 64, HH / 64, EE);    // 44 x 16 x 8
        k_tconv13<<<g, 256>>>(w13);                                // 2
    }
    // fused: mma1 GEMM tiles + w2-transpose tiles + out zeroing, one grid
    k_mma<1><<<dim3(NX_TOTAL, NT_MAX), 256, SMEM_BYTES>>>(out, w2);  // 3
    k_mma<2><<<dim3(HH / 128, NT_MAX), 256, SMEM_BYTES>>>(out, w2);  // 4
}